// round 14
// baseline (speedup 1.0000x reference)
#include <cuda_runtime.h>
#include <cuda_fp16.h>
#include <math.h>

// Problem constants
#define BATCH 8
#define NPOS 1024            // 32x32
#define DIM 128
#define HEADS 8
#define GRID 32              // H = W = 32
#define POSITIONS (BATCH*NPOS)   // 8192

#define GEMM_SMEM 71680      // gemmU: 2x(128x72) + 2x(64x136) halfs; aliases 128x132 f32 U tile
#define GEMMY_SMEM 79872     // gemmY: 3x(64x72) + 3x(64x136) halfs
#define CR_SMEM 16384        // colcum_regions: 1024 pos x 4 dims fp32

// ---------------- scratch (static device memory; no allocs allowed) -------
__device__ float g_S[POSITIONS*DIM];             // row-cumsum image
__device__ float g_P1[DIM*DIM];                  // Wq @ Wk^T
__device__ float g_P2[DIM*DIM];                  // Wv @ Wo
__device__ float g_bu[HEADS*DIM];                // 0.25 * bqkv_h @ P1
__device__ float g_bfinal[DIM];

__device__ __half g_XNh[POSITIONS*DIM];          // layernormed x, fp16
__device__ __half g_Rh[POSITIONS*4*DIM];         // region means fp16 [pos][r][d]
__device__ __half g_Mh[DIM*HEADS*DIM];           // 0.25 * Wqkv_h @ P1, [128][1024]
__device__ __half g_W3h[HEADS*DIM*DIM];          // P2 @ Wout_h, [1024][128]
__device__ __half g_Ch[POSITIONS*HEADS*DIM];     // aggregated context, [8192][1024]

// ---------------- helpers ---------------------------------------------------
__device__ __forceinline__ unsigned smem_u32(const void* p) {
    return (unsigned)__cvta_generic_to_shared(p);
}
__device__ __forceinline__ void ldmatrix_x4(unsigned* r, unsigned addr) {
    asm volatile("ldmatrix.sync.aligned.m8n8.x4.shared.b16 {%0,%1,%2,%3}, [%4];"
        : "=r"(r[0]), "=r"(r[1]), "=r"(r[2]), "=r"(r[3]) : "r"(addr));
}
__device__ __forceinline__ void ldmatrix_x2t(unsigned* r, unsigned addr) {
    asm volatile("ldmatrix.sync.aligned.m8n8.x2.trans.shared.b16 {%0,%1}, [%2];"
        : "=r"(r[0]), "=r"(r[1]) : "r"(addr));
}
__device__ __forceinline__ void mma_f16(float* d, const unsigned* a, const unsigned* b) {
    asm volatile("mma.sync.aligned.m16n8k16.row.col.f32.f16.f16.f32 "
        "{%0,%1,%2,%3}, {%4,%5,%6,%7}, {%8,%9}, {%0,%1,%2,%3};"
        : "+f"(d[0]), "+f"(d[1]), "+f"(d[2]), "+f"(d[3])
        : "r"(a[0]), "r"(a[1]), "r"(a[2]), "r"(a[3]), "r"(b[0]), "r"(b[1]));
}
__device__ __forceinline__ void cp_async16(void* smem_dst, const void* gsrc) {
    asm volatile("cp.async.ca.shared.global [%0], [%1], 16;"
        :: "r"(smem_u32(smem_dst)), "l"(gsrc));
}

// ---------------- 64x64-tile fp32 matmul for weight precompute --------------
template<int MODE>
__device__ void mm64(const float* __restrict__ A, int lda,
                     const float* __restrict__ B, int ldb, int transB,
                     float* __restrict__ C, __half* __restrict__ Ch,
                     int ldc, int row0, int col0, float scale)
{
    __shared__ float As[16][64];
    __shared__ float Bs[16][68];
    const int tid = threadIdx.x;
    const int ty = tid >> 4, tx = tid & 15;
    float acc[4][4];
#pragma unroll
    for (int i = 0; i < 4; i++)
#pragma unroll
        for (int j = 0; j < 4; j++) acc[i][j] = 0.f;

    for (int k0 = 0; k0 < 128; k0 += 16) {
        for (int t = tid; t < 1024; t += 256) {
            int m = t >> 4, kk = t & 15;
            As[kk][m] = A[(row0+m)*lda + k0 + kk];
        }
        for (int t = tid; t < 1024; t += 256) {
            int kk = t >> 6, n = t & 63;
            Bs[kk][n] = transB ? B[(col0+n)*ldb + k0 + kk] : B[(k0+kk)*ldb + col0 + n];
        }
        __syncthreads();
#pragma unroll
        for (int kk = 0; kk < 16; kk++) {
            float a[4], b[4];
#pragma unroll
            for (int i = 0; i < 4; i++) a[i] = As[kk][ty*4+i];
#pragma unroll
            for (int j = 0; j < 4; j++) b[j] = Bs[kk][tx*4+j];
#pragma unroll
            for (int i = 0; i < 4; i++)
#pragma unroll
                for (int j = 0; j < 4; j++) acc[i][j] += a[i]*b[j];
        }
        __syncthreads();
    }
#pragma unroll
    for (int i = 0; i < 4; i++)
#pragma unroll
        for (int j = 0; j < 4; j++) {
            int r = row0 + ty*4 + i, c = col0 + tx*4 + j;
            if (MODE == 0) C[r*ldc + c] = acc[i][j];
            else           Ch[r*ldc + c] = __float2half(acc[i][j] * scale);
        }
}

// ---------------- precompute stage A: P1 = Wq@Wk^T, P2 = Wv@Wo, bfinal ------
__global__ void precompA3(const float* __restrict__ Wq, const float* __restrict__ Wk,
                          const float* __restrict__ Wv, const float* __restrict__ Wo,
                          const float* __restrict__ Wout, const float* __restrict__ bo,
                          const float* __restrict__ bout)
{
    int blk = blockIdx.x;
    if (blk < 4) {
        mm64<0>(Wq, DIM, Wk, DIM, 1, g_P1, 0, DIM, (blk>>1)*64, (blk&1)*64, 1.f);
    } else if (blk < 8) {
        int q = blk - 4;
        mm64<0>(Wv, DIM, Wo, DIM, 0, g_P2, 0, DIM, (q>>1)*64, (q&1)*64, 1.f);
    } else {
        __shared__ float part[256];
        int e = threadIdx.x & 127, half = threadIdx.x >> 7;
        float s = 0.f;
#pragma unroll 8
        for (int c = half*512; c < half*512 + 512; c++) s += bo[c & 127] * Wout[c*128 + e];
        part[threadIdx.x] = s;
        __syncthreads();
        if (half == 0) g_bfinal[e] = part[e] + part[128+e] + bout[e];
    }
}

// ---------------- precompute stage B: M_h, W3_h, bu -------------------------
__global__ void precompB3(const float* __restrict__ Wqkv, const float* __restrict__ bqkv,
                          const float* __restrict__ Wout)
{
    int blk = blockIdx.x;
    if (blk < 32) {
        int h = blk >> 2, q = blk & 3;
        mm64<1>(Wqkv + h*128, 3*HEADS*DIM, g_P1, DIM, 0, 0,
                g_Mh + h*DIM, HEADS*DIM, (q>>1)*64, (q&1)*64, 0.25f);
    } else if (blk < 64) {
        int h = (blk-32) >> 2, q = (blk-32) & 3;
        mm64<1>(g_P2, DIM, Wout + h*DIM*DIM, DIM, 0, 0,
                g_W3h + h*DIM*DIM, DIM, (q>>1)*64, (q&1)*64, 1.f);
    } else {
        for (int o = threadIdx.x; o < HEADS*DIM; o += 256) {
            int h = o >> 7, d2 = o & 127;
            float s = 0.f;
#pragma unroll 8
            for (int c = 0; c < 128; c++) s += bqkv[h*128+c] * g_P1[c*128+d2];
            g_bu[o] = 0.25f * s;
        }
    }
}

// ---------------- fused layernorm + row cumsum ------------------------------
__global__ __launch_bounds__(256) void ln_rowcum(const float* __restrict__ x,
                                                 const float* __restrict__ g,
                                                 const float* __restrict__ b)
{
    __shared__ float xs[32][128];
    const int bh = blockIdx.x;
    const int tid = threadIdx.x;
    const int wid = tid >> 5, lane = tid & 31;

    float4 g4 = ((const float4*)g)[lane];
    float4 b4 = ((const float4*)b)[lane];

#pragma unroll
    for (int i = 0; i < 4; i++) {
        int p = wid*4 + i;
        int row = bh*GRID + p;
        float4 v = ((const float4*)x)[row*32 + lane];
        float s  = v.x + v.y + v.z + v.w;
        float s2 = v.x*v.x + v.y*v.y + v.z*v.z + v.w*v.w;
#pragma unroll
        for (int o = 16; o > 0; o >>= 1) {
            s  += __shfl_xor_sync(0xffffffffu, s, o);
            s2 += __shfl_xor_sync(0xffffffffu, s2, o);
        }
        float mu = s * (1.f/128.f);
        float var = s2 * (1.f/128.f) - mu*mu;
        float inv = rsqrtf(var + 1e-5f);
        float4 xn;
        xn.x = (v.x - mu)*inv*g4.x + b4.x;
        xn.y = (v.y - mu)*inv*g4.y + b4.y;
        xn.z = (v.z - mu)*inv*g4.z + b4.z;
        xn.w = (v.w - mu)*inv*g4.w + b4.w;
        *(float4*)&xs[p][lane*4] = xn;
        *(__half2*)&g_XNh[row*DIM + lane*4]     = __floats2half2_rn(xn.x, xn.y);
        *(__half2*)&g_XNh[row*DIM + lane*4 + 2] = __floats2half2_rn(xn.z, xn.w);
    }
    __syncthreads();
    if (tid < 128) {
        float run = 0.f;
#pragma unroll
        for (int w = 0; w < GRID; w++) {
            run += xs[w][tid];
            g_S[(bh*GRID + w)*DIM + tid] = run;
        }
    }
}

// ---------------- fused column cumsum + region means ------------------------
// Block = (batch, 4-dim chunk): 256 blocks, 16KB smem slab [1024 pos][4],
// stride 4 -> conflict-free scan (addr == lane) and loads.
__global__ __launch_bounds__(256) void colcum_regions()
{
    extern __shared__ float S[];                 // [pos][4]
    const int b  = blockIdx.x >> 5;
    const int d0 = (blockIdx.x & 31) * 4;
    const int tid = threadIdx.x;

    // ---- load slab: 4 positions per thread, float4 each -------------------
#pragma unroll
    for (int i = 0; i < 4; i++) {
        int pos = i*256 + tid;
        *(float4*)&S[pos*4] =
            *(const float4*)&g_S[((size_t)b*NPOS + pos)*DIM + d0];
    }
    __syncthreads();

    // ---- column scan in registers: thread owns (w, dd), 128 active --------
    if (tid < 128) {
        int w = tid >> 2, dd = tid & 3;
        float v[GRID];
#pragma unroll
        for (int h = 0; h < GRID; h++) v[h] = S[(h*GRID + w)*4 + dd];
        float run = 0.f;
#pragma unroll
        for (int h = 0; h < GRID; h++) { run += v[h]; v[h] = run; }
#pragma unroll
        for (int h = 0; h < GRID; h++) S[(h*GRID + w)*4 + dd] = v[h];
    }
    __syncthreads();

    // ---- means phase: thread per position, 4 positions/thread -------------
#pragma unroll 1
    for (int it = 0; it < 4; it++) {
        int pos = it*256 + tid;
        int h = pos >> 5, w = pos & 31;

        float4 z = make_float4(0.f, 0.f, 0.f, 0.f);
        float4 vhw  = *(float4*)&S[(h*GRID + w)*4];
        float4 vhW  = *(float4*)&S[(h*GRID + 31)*4];
        float4 vHw  = *(float4*)&S[(31*GRID + w)*4];
        float4 vHW  = *(float4*)&S[(31*GRID + 31)*4];
        float4 vh1w = z, vh1W = z, vhw1 = z, vHw1 = z, vh1w1 = z;
        if (h > 0) {
            vh1w = *(float4*)&S[((h-1)*GRID + w)*4];
            vh1W = *(float4*)&S[((h-1)*GRID + 31)*4];
            if (w > 0) vh1w1 = *(float4*)&S[((h-1)*GRID + w-1)*4];
        }
        if (w > 0) {
            vhw1 = *(float4*)&S[(h*GRID + w-1)*4];
            vHw1 = *(float4*)&S[(31*GRID + w-1)*4];
        }

        float hp1 = (float)(h+1), wp1 = (float)(w+1);
        float hr = (float)(GRID - h), wr = (float)(GRID - w);
        float i1 = __fdividef(1.f, hp1*wp1);
        float i2 = __fdividef(1.f, hp1*wr);
        float i3 = __fdividef(1.f, hr*wp1);
        float i4 = __fdividef(1.f, hr*wr);

        uint2 o0, o1, o2, o3;
        __half2* p0 = (__half2*)&o0;
        __half2* p1 = (__half2*)&o1;
        __half2* p2 = (__half2*)&o2;
        __half2* p3 = (__half2*)&o3;
        p0[0] = __floats2half2_rn(vhw.x*i1, vhw.y*i1);
        p0[1] = __floats2half2_rn(vhw.z*i1, vhw.w*i1);
        p1[0] = __floats2half2_rn((vhW.x - vhw1.x)*i2, (vhW.y - vhw1.y)*i2);
        p1[1] = __floats2half2_rn((vhW.z - vhw1.z)*i2, (vhW.w - vhw1.w)*i2);
        p2[0] = __floats2half2_rn((vHw.x - vh1w.x)*i3, (vHw.y - vh1w.y)*i3);
        p2[1] = __floats2half2_rn((vHw.z - vh1w.z)*i3, (vHw.w - vh1w.w)*i3);
        p3[0] = __floats2half2_rn((vHW.x - vh1W.x - vHw1.x + vh1w1.x)*i4,
                                  (vHW.y - vh1W.y - vHw1.y + vh1w1.y)*i4);
        p3[1] = __floats2half2_rn((vHW.z - vh1W.z - vHw1.z + vh1w1.z)*i4,
                                  (vHW.w - vh1W.w - vHw1.w + vh1w1.w)*i4);

        __half* R = g_Rh + (size_t)(b*NPOS + pos)*4*DIM + d0;
        *(uint2*)&R[0]     = o0;
        *(uint2*)&R[DIM]   = o1;
        *(uint2*)&R[2*DIM] = o2;
        *(uint2*)&R[3*DIM] = o3;
    }
}

// ---------------- fused: U-GEMM (fp16, K=128) + softmax + aggregate ---------
__global__ __launch_bounds__(256) void gemmU_fused()
{
    extern __shared__ char sbuf[];
    __half* As = (__half*)sbuf;                  // 2 x 128x72
    __half* Bs = (__half*)(sbuf + 36864);        // 2 x 64x136
    float* Uf = (float*)sbuf;                    // 128x132 (aliases A/B)

    const int tid = threadIdx.x;
    const int wid = tid >> 5, lane = tid & 31;
    const int wm = wid & 1, wn = wid >> 1;       // warp tile 64x32
    const int m0 = blockIdx.x * 128;
    const int h  = blockIdx.y;
    const int n0 = h * 128;

    float acc[4][4][4];
#pragma unroll
    for (int mt = 0; mt < 4; mt++)
#pragma unroll
        for (int nt = 0; nt < 4; nt++)
#pragma unroll
            for (int q = 0; q < 4; q++) acc[mt][nt][q] = 0.f;

    auto LOAD = [&](int s, int buf) {
        int k0 = s * 64;
#pragma unroll
        for (int i = 0; i < 4; i++) {
            int c = tid + i*256;
            int row = c >> 3, col8 = (c & 7) * 8;
            cp_async16(As + buf*9216 + row*72 + col8,
                       g_XNh + (m0+row)*DIM + k0 + col8);
        }
#pragma unroll
        for (int i = 0; i < 4; i++) {
            int c = tid + i*256;
            int kr = c >> 4, col8 = (c & 15) * 8;
            cp_async16(Bs + buf*8704 + kr*136 + col8,
                       g_Mh + (k0+kr)*(HEADS*DIM) + n0 + col8);
        }
        asm volatile("cp.async.commit_group;");
    };

    const unsigned as_base = smem_u32(As), bs_base = smem_u32(Bs);
    unsigned a_off[4], b_off[4];
#pragma unroll
    for (int mt = 0; mt < 4; mt++)
        a_off[mt] = ((wm*64 + mt*16 + (lane & 15))*72 + (lane >> 4)*8)*2;
#pragma unroll
    for (int nt = 0; nt < 4; nt++)
        b_off[nt] = ((lane & 15)*136 + wn*32 + nt*8)*2;

    auto COMPUTE = [&](int buf) {
#pragma unroll
        for (int kk = 0; kk < 4; kk++) {
            unsigned af[4][4];
#pragma unroll
            for (int mt = 0; mt < 4; mt++)
                ldmatrix_x4(af[mt], as_base + buf*18432 + a_off[mt] + kk*32);
#pragma unroll
            for (int nt = 0; nt < 4; nt++) {
                unsigned bfr[2];
                ldmatrix_x2t(bfr, bs_base + buf*17408 + b_off[nt] + kk*4352);
#pragma unroll
                for (int mt = 0; mt < 4; mt++) mma_f16(acc[mt][nt], af[mt], bfr);
            }
        }
    };

    LOAD(0, 0);
    LOAD(1, 1);
    asm volatile("cp.async.wait_group 1;");
    __syncthreads();
    COMPUTE(0);
    __syncthreads();
    asm volatile("cp.async.wait_group 0;");
    __syncthreads();
    COMPUTE(1);
    __syncthreads();

    // ---- write U tile (acc + scaled bias) into smem fp32 ------------------
    const int tr = lane >> 2, tc = (lane & 3)*2;
    const int r0 = wm*64, c0 = wn*32;
#pragma unroll
    for (int mt = 0; mt < 4; mt++)
#pragma unroll
        for (int nt = 0; nt < 4; nt++) {
            int row = r0 + mt*16 + tr, col = c0 + nt*8 + tc;
            float b0 = g_bu[n0 + col], b1 = g_bu[n0 + col + 1];
            *(float2*)&Uf[row*132 + col] =
                make_float2(acc[mt][nt][0] + b0, acc[mt][nt][1] + b1);
            *(float2*)&Uf[(row+8)*132 + col] =
                make_float2(acc[mt][nt][2] + b0, acc[mt][nt][3] + b1);
        }
    __syncthreads();

    // ---- per-warp: scores (0.25 pre-folded), softmax, aggregate -----------
    for (int i = 0; i < 16; i++) {
        int p = wid*16 + i;
        int gpos = m0 + p;
        const __half* Rp = g_Rh + (size_t)gpos*4*DIM;
        float2 f[2][4];
        float s0 = 0.f, s1 = 0.f, s2 = 0.f, s3 = 0.f;
#pragma unroll
        for (int c2 = 0; c2 < 2; c2++) {
            int d = lane*2 + c2*64;
            float2 u = *(float2*)&Uf[p*132 + d];
            f[c2][0] = __half22float2(*(const __half2*)&Rp[d]);
            f[c2][1] = __half22float2(*(const __half2*)&Rp[DIM + d]);
            f[c2][2] = __half22float2(*(const __half2*)&Rp[2*DIM + d]);
            f[c2][3] = __half22float2(*(const __half2*)&Rp[3*DIM + d]);
            s0 += u.x*f[c2][0].x + u.y*f[c2][0].y;
            s1 += u.x*f[c2][1].x + u.y*f[c2][1].y;
            s2 += u.x*f[c2][2].x + u.y*f[c2][2].y;
            s3 += u.x*f[c2][3].x + u.y*f[c2][3].y;
        }
#pragma unroll
        for (int o = 16; o > 0; o >>= 1) {
            s0 += __shfl_xor_sync(0xffffffffu, s0, o);
            s1 += __shfl_xor_sync(0xffffffffu, s1, o);
            s2 += __shfl_xor_sync(0xffffffffu, s2, o);
            s3 += __shfl_xor_sync(0xffffffffu, s3, o);
        }
        float m = fmaxf(fmaxf(s0, s1), fmaxf(s2, s3));
        float e0 = expf(s0 - m), e1 = expf(s1 - m), e2 = expf(s2 - m), e3 = expf(s3 - m);
        float inv = 1.f / (e0 + e1 + e2 + e3);
        float p0 = e0*inv, p1 = e1*inv, p2 = e2*inv, p3 = e3*inv;
#pragma unroll
        for (int c2 = 0; c2 < 2; c2++) {
            int d = lane*2 + c2*64;
            float cx = p0*f[c2][0].x + p1*f[c2][1].x + p2*f[c2][2].x + p3*f[c2][3].x;
            float cy = p0*f[c2][0].y + p1*f[c2][1].y + p2*f[c2][2].y + p3*f[c2][3].y;
            *(__half2*)&g_Ch[(size_t)gpos*(HEADS*DIM) + n0 + d] =
                __floats2half2_rn(cx, cy);
        }
    }
}

// ---------------- Y = C @ W3cat + bfinal -> out (3-stage pipeline) ----------
__global__ __launch_bounds__(256) void gemmY3(float* __restrict__ out)
{
    extern __shared__ char sbuf[];
    __half* As = (__half*)sbuf;                  // 3 x 64x72
    __half* Bs = (__half*)(sbuf + 27648);        // 3 x 64x136

    const int tid = threadIdx.x;
    const int wid = tid >> 5, lane = tid & 31;
    const int wm = wid & 1, wn = wid >> 1;       // warp tile 32x32
    const int m0 = blockIdx.x * 64;

    float acc[2][4][4];
#pragma unroll
    for (int mt = 0; mt < 2; mt++)
#pragma unroll
        for (int nt = 0; nt < 4; nt++)
#pragma unroll
            for (int q = 0; q < 4; q++) acc[mt][nt][q] = 0.f;

    auto LOAD = [&](int s, int buf) {
        int k0 = s * 64;
#pragma unroll
        for (int i = 0; i < 2; i++) {
            int c = tid + i*256;
            int row = c >> 3, col8 = (c & 7) * 8;
            cp_async16(As + buf*4608 + row*72 + col8,
                       g_Ch + (size_t)(m0+row)*(HEADS*DIM) + k0 + col8);
        }
#pragma unroll
        for (int i = 0; i < 4; i++) {
            int c = tid + i*256;
            int kr = c >> 4, col8 = (c & 15) * 8;
            cp_async16(Bs + buf*8704 + kr*136 + col8,
                       g_W3h + (k0+kr)*DIM + col8);
        }
        asm volatile("cp.async.commit_group;");
    };

    const unsigned as_base = smem_u32(As), bs_base = smem_u32(Bs);
    unsigned a_off[2], b_off[4];
#pragma unroll
    for (int mt = 0; mt < 2; mt++)
        a_off[mt] = ((wm*32 + mt*16 + (lane & 15))*72 + (lane >> 4)*8)*2;
#pragma unroll
    for (int nt = 0; nt < 4; nt++)
        b_off[nt] = ((lane & 15)*136 + wn*32 + nt*8)*2;

    auto COMPUTE = [&](int buf) {
#pragma unroll
        for (int kk = 0; kk < 4; kk++) {
            unsigned af[2][4];
#pragma unroll
            for (int mt = 0; mt < 2; mt++)
                ldmatrix_x4(af[mt], as_base + buf*9216 + a_off[mt] + kk*32);
#pragma unroll
            for (int nt = 0; nt < 4; nt++) {
                unsigned bfr[2];
                ldmatrix_x2t(bfr, bs_base + buf*17408 + b_off[nt] + kk*4352);
#pragma unroll
                for (int mt = 0; mt < 2; mt++) mma_f16(acc[mt][nt], af[mt], bfr);
            }
        }
    };

    LOAD(0, 0);
    LOAD(1, 1);
    for (int s = 0; s < 16; s++) {
        if (s < 15) asm volatile("cp.async.wait_group 1;");
        else        asm volatile("cp.async.wait_group 0;");
        __syncthreads();
        if (s < 14) LOAD(s+2, (s+2)%3);
        COMPUTE(s%3);
    }

    const int tr = lane >> 2, tc = (lane & 3)*2;
#pragma unroll
    for (int mt = 0; mt < 2; mt++)
#pragma unroll
        for (int nt = 0; nt < 4; nt++) {
            int row = m0 + wm*32 + mt*16 + tr, col = wn*32 + nt*8 + tc;
            float b0 = g_bfinal[col], b1 = g_bfinal[col+1];
            *(float2*)&out[(size_t)row*DIM + col] =
                make_float2(acc[mt][nt][0] + b0, acc[mt][nt][1] + b1);
            *(float2*)&out[(size_t)(row+8)*DIM + col] =
                make_float2(acc[mt][nt][2] + b0, acc[mt][nt][3] + b1);
        }
}

// ---------------- launch -----------------------------------------------------
extern "C" void kernel_launch(void* const* d_in, const int* in_sizes, int n_in,
                              void* d_out, int out_size)
{
    const float* x    = (const float*)d_in[0];
    const float* ln_g = (const float*)d_in[1];
    const float* ln_b = (const float*)d_in[2];
    const float* Wqkv = (const float*)d_in[3];
    const float* bqkv = (const float*)d_in[4];
    const float* Wq   = (const float*)d_in[5];
    const float* Wk   = (const float*)d_in[6];
    const float* Wv   = (const float*)d_in[7];
    const float* Wo   = (const float*)d_in[8];
    const float* bo   = (const float*)d_in[9];
    const float* Wout = (const float*)d_in[10];
    const float* bout = (const float*)d_in[11];
    float* out = (float*)d_out;

    // One-time setup (first call is the non-captured correctness run).
    static cudaStream_t s_side = nullptr;
    static cudaEvent_t s_fork = nullptr, s_join = nullptr;
    if (s_side == nullptr) {
        cudaStreamCreateWithFlags(&s_side, cudaStreamNonBlocking);
        cudaEventCreateWithFlags(&s_fork, cudaEventDisableTiming);
        cudaEventCreateWithFlags(&s_join, cudaEventDisableTiming);
        cudaFuncSetAttribute(gemmU_fused, cudaFuncAttributeMaxDynamicSharedMemorySize, GEMM_SMEM);
        cudaFuncSetAttribute(gemmY3,      cudaFuncAttributeMaxDynamicSharedMemorySize, GEMMY_SMEM);
        cudaFuncSetAttribute(colcum_regions, cudaFuncAttributeMaxDynamicSharedMemorySize, CR_SMEM);
    }

    // Fork: weight precompute on side stream, data chain on main stream.
    cudaEventRecord(s_fork, 0);
    cudaStreamWaitEvent(s_side, s_fork, 0);

    precompA3<<<9, 256, 0, s_side>>>(Wq, Wk, Wv, Wo, Wout, bo, bout);
    precompB3<<<65, 256, 0, s_side>>>(Wqkv, bqkv, Wout);
    cudaEventRecord(s_join, s_side);

    ln_rowcum<<<BATCH*GRID, 256>>>(x, ln_g, ln_b);
    colcum_regions<<<BATCH*32, 256, CR_SMEM>>>();

    // Join: gemmU needs M/bu (side) + XN/regions (main).
    cudaStreamWaitEvent(0, s_join, 0);

    gemmU_fused<<<dim3(POSITIONS/128, HEADS), 256, GEMM_SMEM>>>();
    gemmY3<<<POSITIONS/64, 256, GEMMY_SMEM>>>(out);
}

// round 15
// speedup vs baseline: 1.0840x; 1.0840x over previous
#include <cuda_runtime.h>
#include <cuda_fp16.h>
#include <math.h>

// Problem constants
#define BATCH 8
#define NPOS 1024            // 32x32
#define DIM 128
#define HEADS 8
#define GRID 32              // H = W = 32
#define POSITIONS (BATCH*NPOS)   // 8192

#define GEMM_SMEM 71680      // gemmU: 2x(128x72) As + 2x(64x136) Bs; Uf(fp16 128x136) aliases Bs
#define GEMMY_SMEM 79872     // gemmY: 3x(64x72) + 3x(64x136) halfs
#define CR_SMEM 49152        // colcum_regions: 1024 pos x (8 dims + 4 pad) floats

// ---------------- scratch (static device memory; no allocs allowed) -------
__device__ float g_S[POSITIONS*DIM];             // row-cumsum image
__device__ float g_P1[DIM*DIM];                  // Wq @ Wk^T
__device__ float g_P2[DIM*DIM];                  // Wv @ Wo
__device__ float g_bu[HEADS*DIM];                // 0.25 * bqkv_h @ P1
__device__ float g_bfinal[DIM];

__device__ __half g_XNh[POSITIONS*DIM];          // layernormed x, fp16
__device__ __half g_Rh[POSITIONS*4*DIM];         // region means fp16 [pos][r][d]
__device__ __half g_Mh[DIM*HEADS*DIM];           // 0.25 * Wqkv_h @ P1, [128][1024]
__device__ __half g_W3h[HEADS*DIM*DIM];          // P2 @ Wout_h, [1024][128]
__device__ __half g_Ch[POSITIONS*HEADS*DIM];     // aggregated context, [8192][1024]

// ---------------- helpers ---------------------------------------------------
__device__ __forceinline__ unsigned smem_u32(const void* p) {
    return (unsigned)__cvta_generic_to_shared(p);
}
__device__ __forceinline__ void ldmatrix_x4(unsigned* r, unsigned addr) {
    asm volatile("ldmatrix.sync.aligned.m8n8.x4.shared.b16 {%0,%1,%2,%3}, [%4];"
        : "=r"(r[0]), "=r"(r[1]), "=r"(r[2]), "=r"(r[3]) : "r"(addr));
}
__device__ __forceinline__ void ldmatrix_x2t(unsigned* r, unsigned addr) {
    asm volatile("ldmatrix.sync.aligned.m8n8.x2.trans.shared.b16 {%0,%1}, [%2];"
        : "=r"(r[0]), "=r"(r[1]) : "r"(addr));
}
__device__ __forceinline__ void mma_f16(float* d, const unsigned* a, const unsigned* b) {
    asm volatile("mma.sync.aligned.m16n8k16.row.col.f32.f16.f16.f32 "
        "{%0,%1,%2,%3}, {%4,%5,%6,%7}, {%8,%9}, {%0,%1,%2,%3};"
        : "+f"(d[0]), "+f"(d[1]), "+f"(d[2]), "+f"(d[3])
        : "r"(a[0]), "r"(a[1]), "r"(a[2]), "r"(a[3]), "r"(b[0]), "r"(b[1]));
}
__device__ __forceinline__ void cp_async16(void* smem_dst, const void* gsrc) {
    asm volatile("cp.async.ca.shared.global [%0], [%1], 16;"
        :: "r"(smem_u32(smem_dst)), "l"(gsrc));
}

// ---------------- 64x64-tile fp32 matmul for weight precompute --------------
template<int MODE>
__device__ void mm64(const float* __restrict__ A, int lda,
                     const float* __restrict__ B, int ldb, int transB,
                     float* __restrict__ C, __half* __restrict__ Ch,
                     int ldc, int row0, int col0, float scale)
{
    __shared__ float As[16][64];
    __shared__ float Bs[16][68];
    const int tid = threadIdx.x;
    const int ty = tid >> 4, tx = tid & 15;
    float acc[4][4];
#pragma unroll
    for (int i = 0; i < 4; i++)
#pragma unroll
        for (int j = 0; j < 4; j++) acc[i][j] = 0.f;

    for (int k0 = 0; k0 < 128; k0 += 16) {
        for (int t = tid; t < 1024; t += 256) {
            int m = t >> 4, kk = t & 15;
            As[kk][m] = A[(row0+m)*lda + k0 + kk];
        }
        for (int t = tid; t < 1024; t += 256) {
            int kk = t >> 6, n = t & 63;
            Bs[kk][n] = transB ? B[(col0+n)*ldb + k0 + kk] : B[(k0+kk)*ldb + col0 + n];
        }
        __syncthreads();
#pragma unroll
        for (int kk = 0; kk < 16; kk++) {
            float a[4], b[4];
#pragma unroll
            for (int i = 0; i < 4; i++) a[i] = As[kk][ty*4+i];
#pragma unroll
            for (int j = 0; j < 4; j++) b[j] = Bs[kk][tx*4+j];
#pragma unroll
            for (int i = 0; i < 4; i++)
#pragma unroll
                for (int j = 0; j < 4; j++) acc[i][j] += a[i]*b[j];
        }
        __syncthreads();
    }
#pragma unroll
    for (int i = 0; i < 4; i++)
#pragma unroll
        for (int j = 0; j < 4; j++) {
            int r = row0 + ty*4 + i, c = col0 + tx*4 + j;
            if (MODE == 0) C[r*ldc + c] = acc[i][j];
            else           Ch[r*ldc + c] = __float2half(acc[i][j] * scale);
        }
}

// ---------------- precompute stage A: P1 = Wq@Wk^T, P2 = Wv@Wo, bfinal ------
__global__ void precompA3(const float* __restrict__ Wq, const float* __restrict__ Wk,
                          const float* __restrict__ Wv, const float* __restrict__ Wo,
                          const float* __restrict__ Wout, const float* __restrict__ bo,
                          const float* __restrict__ bout)
{
    int blk = blockIdx.x;
    if (blk < 4) {
        mm64<0>(Wq, DIM, Wk, DIM, 1, g_P1, 0, DIM, (blk>>1)*64, (blk&1)*64, 1.f);
    } else if (blk < 8) {
        int q = blk - 4;
        mm64<0>(Wv, DIM, Wo, DIM, 0, g_P2, 0, DIM, (q>>1)*64, (q&1)*64, 1.f);
    } else {
        __shared__ float part[256];
        int e = threadIdx.x & 127, half = threadIdx.x >> 7;
        float s = 0.f;
#pragma unroll 8
        for (int c = half*512; c < half*512 + 512; c++) s += bo[c & 127] * Wout[c*128 + e];
        part[threadIdx.x] = s;
        __syncthreads();
        if (half == 0) g_bfinal[e] = part[e] + part[128+e] + bout[e];
    }
}

// ---------------- precompute stage B: M_h, W3_h, bu -------------------------
__global__ void precompB3(const float* __restrict__ Wqkv, const float* __restrict__ bqkv,
                          const float* __restrict__ Wout)
{
    int blk = blockIdx.x;
    if (blk < 32) {
        int h = blk >> 2, q = blk & 3;
        mm64<1>(Wqkv + h*128, 3*HEADS*DIM, g_P1, DIM, 0, 0,
                g_Mh + h*DIM, HEADS*DIM, (q>>1)*64, (q&1)*64, 0.25f);
    } else if (blk < 64) {
        int h = (blk-32) >> 2, q = (blk-32) & 3;
        mm64<1>(g_P2, DIM, Wout + h*DIM*DIM, DIM, 0, 0,
                g_W3h + h*DIM*DIM, DIM, (q>>1)*64, (q&1)*64, 1.f);
    } else {
        for (int o = threadIdx.x; o < HEADS*DIM; o += 256) {
            int h = o >> 7, d2 = o & 127;
            float s = 0.f;
#pragma unroll 8
            for (int c = 0; c < 128; c++) s += bqkv[h*128+c] * g_P1[c*128+d2];
            g_bu[o] = 0.25f * s;
        }
    }
}

// ---------------- fused layernorm + row cumsum ------------------------------
__global__ __launch_bounds__(256) void ln_rowcum(const float* __restrict__ x,
                                                 const float* __restrict__ g,
                                                 const float* __restrict__ b)
{
    __shared__ float xs[32][128];
    const int bh = blockIdx.x;
    const int tid = threadIdx.x;
    const int wid = tid >> 5, lane = tid & 31;

    float4 g4 = ((const float4*)g)[lane];
    float4 b4 = ((const float4*)b)[lane];

#pragma unroll
    for (int i = 0; i < 4; i++) {
        int p = wid*4 + i;
        int row = bh*GRID + p;
        float4 v = ((const float4*)x)[row*32 + lane];
        float s  = v.x + v.y + v.z + v.w;
        float s2 = v.x*v.x + v.y*v.y + v.z*v.z + v.w*v.w;
#pragma unroll
        for (int o = 16; o > 0; o >>= 1) {
            s  += __shfl_xor_sync(0xffffffffu, s, o);
            s2 += __shfl_xor_sync(0xffffffffu, s2, o);
        }
        float mu = s * (1.f/128.f);
        float var = s2 * (1.f/128.f) - mu*mu;
        float inv = rsqrtf(var + 1e-5f);
        float4 xn;
        xn.x = (v.x - mu)*inv*g4.x + b4.x;
        xn.y = (v.y - mu)*inv*g4.y + b4.y;
        xn.z = (v.z - mu)*inv*g4.z + b4.z;
        xn.w = (v.w - mu)*inv*g4.w + b4.w;
        *(float4*)&xs[p][lane*4] = xn;
        *(__half2*)&g_XNh[row*DIM + lane*4]     = __floats2half2_rn(xn.x, xn.y);
        *(__half2*)&g_XNh[row*DIM + lane*4 + 2] = __floats2half2_rn(xn.z, xn.w);
    }
    __syncthreads();
    if (tid < 128) {
        float run = 0.f;
#pragma unroll
        for (int w = 0; w < GRID; w++) {
            run += xs[w][tid];
            g_S[(bh*GRID + w)*DIM + tid] = run;
        }
    }
}

// ---------------- fused column cumsum + region means (round-10 version) -----
__global__ __launch_bounds__(256) void colcum_regions()
{
    extern __shared__ float S[];                 // [pos][12], dims at [0..7]
    const int b  = blockIdx.x >> 4;
    const int d0 = (blockIdx.x & 15) * 8;
    const int tid = threadIdx.x;

#pragma unroll
    for (int i = 0; i < 4; i++) {
        int pos = i*256 + tid;
        const float4* src = (const float4*)&g_S[((size_t)b*NPOS + pos)*DIM + d0];
        float4 v0 = src[0], v1 = src[1];
        *(float4*)&S[pos*12]     = v0;
        *(float4*)&S[pos*12 + 4] = v1;
    }
    __syncthreads();

    {
        int w = tid >> 3, dd = tid & 7;
        float v[GRID];
#pragma unroll
        for (int h = 0; h < GRID; h++) v[h] = S[(h*GRID + w)*12 + dd];
        float run = 0.f;
#pragma unroll
        for (int h = 0; h < GRID; h++) { run += v[h]; v[h] = run; }
#pragma unroll
        for (int h = 0; h < GRID; h++) S[(h*GRID + w)*12 + dd] = v[h];
    }
    __syncthreads();

    if (tid < 128) {
        const int w  = tid >> 2;
        const int dd = (tid & 3) * 2;
        const float wp1 = (float)(w + 1), wr = (float)(GRID - w);

        float2 fHw  = *(float2*)&S[(31*GRID + w)*12 + dd];
        float2 fHW  = *(float2*)&S[(31*GRID + 31)*12 + dd];
        float2 fHw1 = make_float2(0.f, 0.f);
        if (w > 0) fHw1 = *(float2*)&S[(31*GRID + w-1)*12 + dd];

        float2 p_hw = make_float2(0.f, 0.f);
        float2 p_hw1 = make_float2(0.f, 0.f);
        float2 p_hW = make_float2(0.f, 0.f);

#pragma unroll 4
        for (int h = 0; h < GRID; h++) {
            float2 c_hw  = *(float2*)&S[(h*GRID + w)*12 + dd];
            float2 c_hW  = *(float2*)&S[(h*GRID + 31)*12 + dd];
            float2 c_hw1 = make_float2(0.f, 0.f);
            if (w > 0) c_hw1 = *(float2*)&S[(h*GRID + w-1)*12 + dd];

            float hp1 = (float)(h + 1), hr = (float)(GRID - h);
            float i1 = __fdividef(1.f, hp1*wp1);
            float i2 = __fdividef(1.f, hp1*wr);
            float i3 = __fdividef(1.f, hr*wp1);
            float i4 = __fdividef(1.f, hr*wr);

            __half* R = g_Rh + ((size_t)(b*NPOS + h*GRID + w))*4*DIM + d0 + dd;
            *(__half2*)&R[0]     = __floats2half2_rn(c_hw.x*i1, c_hw.y*i1);
            *(__half2*)&R[DIM]   = __floats2half2_rn((c_hW.x - c_hw1.x)*i2,
                                                     (c_hW.y - c_hw1.y)*i2);
            *(__half2*)&R[2*DIM] = __floats2half2_rn((fHw.x - p_hw.x)*i3,
                                                     (fHw.y - p_hw.y)*i3);
            *(__half2*)&R[3*DIM] = __floats2half2_rn(
                (fHW.x - p_hW.x - fHw1.x + p_hw1.x)*i4,
                (fHW.y - p_hW.y - fHw1.y + p_hw1.y)*i4);

            p_hw = c_hw; p_hw1 = c_hw1; p_hW = c_hW;
        }
    }
}

// ---------------- fused: U-GEMM, 2 heads per block + softmax + aggregate ----
// Block = 128 positions x heads (y, y+4). XN tile persists across both heads.
// Uf staged fp16, aliasing the Bs region.
__global__ __launch_bounds__(256) void gemmU_fused()
{
    extern __shared__ char sbuf[];
    __half* As = (__half*)sbuf;                  // 2 x 128x72
    __half* Bs = (__half*)(sbuf + 36864);        // 2 x 64x136
    __half* Uf = (__half*)(sbuf + 36864);        // 128x136 fp16 (aliases Bs)

    const int tid = threadIdx.x;
    const int wid = tid >> 5, lane = tid & 31;
    const int wm = wid & 1, wn = wid >> 1;       // warp tile 64x32
    const int m0 = blockIdx.x * 128;

    auto LOAD_A = [&](int s, int buf) {
        int k0 = s * 64;
#pragma unroll
        for (int i = 0; i < 4; i++) {
            int c = tid + i*256;
            int row = c >> 3, col8 = (c & 7) * 8;
            cp_async16(As + buf*9216 + row*72 + col8,
                       g_XNh + (m0+row)*DIM + k0 + col8);
        }
    };
    auto LOAD_B = [&](int n0, int s, int buf) {
        int k0 = s * 64;
#pragma unroll
        for (int i = 0; i < 4; i++) {
            int c = tid + i*256;
            int kr = c >> 4, col8 = (c & 15) * 8;
            cp_async16(Bs + buf*8704 + kr*136 + col8,
                       g_Mh + (k0+kr)*(HEADS*DIM) + n0 + col8);
        }
    };

    const unsigned as_base = smem_u32(As), bs_base = smem_u32(Bs);
    unsigned a_off[4], b_off[4];
#pragma unroll
    for (int mt = 0; mt < 4; mt++)
        a_off[mt] = ((wm*64 + mt*16 + (lane & 15))*72 + (lane >> 4)*8)*2;
#pragma unroll
    for (int nt = 0; nt < 4; nt++)
        b_off[nt] = ((lane & 15)*136 + wn*32 + nt*8)*2;

    const int tr = lane >> 2, tc = (lane & 3)*2;
    const int r0 = wm*64, c0 = wn*32;

    // prologue: A (both stages) + B for first head
    {
        int n0 = blockIdx.y * 128;
        LOAD_A(0, 0); LOAD_B(n0, 0, 0);
        asm volatile("cp.async.commit_group;");
        LOAD_A(1, 1); LOAD_B(n0, 1, 1);
        asm volatile("cp.async.commit_group;");
    }

    for (int hh = 0; hh < 2; hh++) {
        const int h  = blockIdx.y + hh*4;
        const int n0 = h * 128;

        float acc[4][4][4];
#pragma unroll
        for (int mt = 0; mt < 4; mt++)
#pragma unroll
            for (int nt = 0; nt < 4; nt++)
#pragma unroll
                for (int q = 0; q < 4; q++) acc[mt][nt][q] = 0.f;

        auto COMPUTE = [&](int buf) {
#pragma unroll
            for (int kk = 0; kk < 4; kk++) {
                unsigned af[4][4];
#pragma unroll
                for (int mt = 0; mt < 4; mt++)
                    ldmatrix_x4(af[mt], as_base + buf*18432 + a_off[mt] + kk*32);
#pragma unroll
                for (int nt = 0; nt < 4; nt++) {
                    unsigned bfr[2];
                    ldmatrix_x2t(bfr, bs_base + buf*17408 + b_off[nt] + kk*4352);
#pragma unroll
                    for (int mt = 0; mt < 4; mt++) mma_f16(acc[mt][nt], af[mt], bfr);
                }
            }
        };

        asm volatile("cp.async.wait_group 1;");
        __syncthreads();
        COMPUTE(0);
        __syncthreads();
        asm volatile("cp.async.wait_group 0;");
        __syncthreads();
        COMPUTE(1);
        __syncthreads();                           // done reading Bs

        // ---- stage U (acc + bias) as fp16 into Uf (overwrites Bs) ---------
#pragma unroll
        for (int mt = 0; mt < 4; mt++)
#pragma unroll
            for (int nt = 0; nt < 4; nt++) {
                int row = r0 + mt*16 + tr, col = c0 + nt*8 + tc;
                float b0 = g_bu[n0 + col], b1 = g_bu[n0 + col + 1];
                *(__half2*)&Uf[row*136 + col] =
                    __floats2half2_rn(acc[mt][nt][0] + b0, acc[mt][nt][1] + b1);
                *(__half2*)&Uf[(row+8)*136 + col] =
                    __floats2half2_rn(acc[mt][nt][2] + b0, acc[mt][nt][3] + b1);
            }
        __syncthreads();                           // Uf complete

        // ---- per-warp epilogue: scores, softmax, aggregate ----------------
        for (int i = 0; i < 16; i++) {
            int p = wid*16 + i;
            int gpos = m0 + p;
            const __half* Rp = g_Rh + (size_t)gpos*4*DIM;
            float2 f[2][4];
            float s0 = 0.f, s1 = 0.f, s2 = 0.f, s3 = 0.f;
#pragma unroll
            for (int c2 = 0; c2 < 2; c2++) {
                int d = lane*2 + c2*64;
                float2 u = __half22float2(*(const __half2*)&Uf[p*136 + d]);
                f[c2][0] = __half22float2(*(const __half2*)&Rp[d]);
                f[c2][1] = __half22float2(*(const __half2*)&Rp[DIM + d]);
                f[c2][2] = __half22float2(*(const __half2*)&Rp[2*DIM + d]);
                f[c2][3] = __half22float2(*(const __half2*)&Rp[3*DIM + d]);
                s0 += u.x*f[c2][0].x + u.y*f[c2][0].y;
                s1 += u.x*f[c2][1].x + u.y*f[c2][1].y;
                s2 += u.x*f[c2][2].x + u.y*f[c2][2].y;
                s3 += u.x*f[c2][3].x + u.y*f[c2][3].y;
            }
#pragma unroll
            for (int o = 16; o > 0; o >>= 1) {
                s0 += __shfl_xor_sync(0xffffffffu, s0, o);
                s1 += __shfl_xor_sync(0xffffffffu, s1, o);
                s2 += __shfl_xor_sync(0xffffffffu, s2, o);
                s3 += __shfl_xor_sync(0xffffffffu, s3, o);
            }
            float m = fmaxf(fmaxf(s0, s1), fmaxf(s2, s3));
            float e0 = expf(s0 - m), e1 = expf(s1 - m);
            float e2 = expf(s2 - m), e3 = expf(s3 - m);
            float inv = 1.f / (e0 + e1 + e2 + e3);
            float p0 = e0*inv, p1 = e1*inv, p2 = e2*inv, p3 = e3*inv;
#pragma unroll
            for (int c2 = 0; c2 < 2; c2++) {
                int d = lane*2 + c2*64;
                float cx = p0*f[c2][0].x + p1*f[c2][1].x + p2*f[c2][2].x + p3*f[c2][3].x;
                float cy = p0*f[c2][0].y + p1*f[c2][1].y + p2*f[c2][2].y + p3*f[c2][3].y;
                *(__half2*)&g_Ch[(size_t)gpos*(HEADS*DIM) + n0 + d] =
                    __floats2half2_rn(cx, cy);
            }
        }

        // ---- prefetch B for second head (Uf dead after this sync) ---------
        if (hh == 0) {
            __syncthreads();                       // all warps done with Uf
            int n1 = (blockIdx.y + 4) * 128;
            LOAD_B(n1, 0, 0);
            asm volatile("cp.async.commit_group;");
            LOAD_B(n1, 1, 1);
            asm volatile("cp.async.commit_group;");
        }
    }
}

// ---------------- Y = C @ W3cat + bfinal -> out (3-stage pipeline) ----------
__global__ __launch_bounds__(256) void gemmY3(float* __restrict__ out)
{
    extern __shared__ char sbuf[];
    __half* As = (__half*)sbuf;                  // 3 x 64x72
    __half* Bs = (__half*)(sbuf + 27648);        // 3 x 64x136

    const int tid = threadIdx.x;
    const int wid = tid >> 5, lane = tid & 31;
    const int wm = wid & 1, wn = wid >> 1;       // warp tile 32x32
    const int m0 = blockIdx.x * 64;

    float acc[2][4][4];
#pragma unroll
    for (int mt = 0; mt < 2; mt++)
#pragma unroll
        for (int nt = 0; nt < 4; nt++)
#pragma unroll
            for (int q = 0; q < 4; q++) acc[mt][nt][q] = 0.f;

    auto LOAD = [&](int s, int buf) {
        int k0 = s * 64;
#pragma unroll
        for (int i = 0; i < 2; i++) {
            int c = tid + i*256;
            int row = c >> 3, col8 = (c & 7) * 8;
            cp_async16(As + buf*4608 + row*72 + col8,
                       g_Ch + (size_t)(m0+row)*(HEADS*DIM) + k0 + col8);
        }
#pragma unroll
        for (int i = 0; i < 4; i++) {
            int c = tid + i*256;
            int kr = c >> 4, col8 = (c & 15) * 8;
            cp_async16(Bs + buf*8704 + kr*136 + col8,
                       g_W3h + (k0+kr)*DIM + col8);
        }
        asm volatile("cp.async.commit_group;");
    };

    const unsigned as_base = smem_u32(As), bs_base = smem_u32(Bs);
    unsigned a_off[2], b_off[4];
#pragma unroll
    for (int mt = 0; mt < 2; mt++)
        a_off[mt] = ((wm*32 + mt*16 + (lane & 15))*72 + (lane >> 4)*8)*2;
#pragma unroll
    for (int nt = 0; nt < 4; nt++)
        b_off[nt] = ((lane & 15)*136 + wn*32 + nt*8)*2;

    auto COMPUTE = [&](int buf) {
#pragma unroll
        for (int kk = 0; kk < 4; kk++) {
            unsigned af[2][4];
#pragma unroll
            for (int mt = 0; mt < 2; mt++)
                ldmatrix_x4(af[mt], as_base + buf*9216 + a_off[mt] + kk*32);
#pragma unroll
            for (int nt = 0; nt < 4; nt++) {
                unsigned bfr[2];
                ldmatrix_x2t(bfr, bs_base + buf*17408 + b_off[nt] + kk*4352);
#pragma unroll
                for (int mt = 0; mt < 2; mt++) mma_f16(acc[mt][nt], af[mt], bfr);
            }
        }
    };

    LOAD(0, 0);
    LOAD(1, 1);
    for (int s = 0; s < 16; s++) {
        if (s < 15) asm volatile("cp.async.wait_group 1;");
        else        asm volatile("cp.async.wait_group 0;");
        __syncthreads();
        if (s < 14) LOAD(s+2, (s+2)%3);
        COMPUTE(s%3);
    }

    const int tr = lane >> 2, tc = (lane & 3)*2;
#pragma unroll
    for (int mt = 0; mt < 2; mt++)
#pragma unroll
        for (int nt = 0; nt < 4; nt++) {
            int row = m0 + wm*32 + mt*16 + tr, col = wn*32 + nt*8 + tc;
            float b0 = g_bfinal[col], b1 = g_bfinal[col+1];
            *(float2*)&out[(size_t)row*DIM + col] =
                make_float2(acc[mt][nt][0] + b0, acc[mt][nt][1] + b1);
            *(float2*)&out[(size_t)(row+8)*DIM + col] =
                make_float2(acc[mt][nt][2] + b0, acc[mt][nt][3] + b1);
        }
}

// ---------------- launch -----------------------------------------------------
extern "C" void kernel_launch(void* const* d_in, const int* in_sizes, int n_in,
                              void* d_out, int out_size)
{
    const float* x    = (const float*)d_in[0];
    const float* ln_g = (const float*)d_in[1];
    const float* ln_b = (const float*)d_in[2];
    const float* Wqkv = (const float*)d_in[3];
    const float* bqkv = (const float*)d_in[4];
    const float* Wq   = (const float*)d_in[5];
    const float* Wk   = (const float*)d_in[6];
    const float* Wv   = (const float*)d_in[7];
    const float* Wo   = (const float*)d_in[8];
    const float* bo   = (const float*)d_in[9];
    const float* Wout = (const float*)d_in[10];
    const float* bout = (const float*)d_in[11];
    float* out = (float*)d_out;

    // One-time setup (first call is the non-captured correctness run).
    static cudaStream_t s_side = nullptr;
    static cudaEvent_t s_fork = nullptr, s_join = nullptr;
    if (s_side == nullptr) {
        cudaStreamCreateWithFlags(&s_side, cudaStreamNonBlocking);
        cudaEventCreateWithFlags(&s_fork, cudaEventDisableTiming);
        cudaEventCreateWithFlags(&s_join, cudaEventDisableTiming);
        cudaFuncSetAttribute(gemmU_fused, cudaFuncAttributeMaxDynamicSharedMemorySize, GEMM_SMEM);
        cudaFuncSetAttribute(gemmY3,      cudaFuncAttributeMaxDynamicSharedMemorySize, GEMMY_SMEM);
        cudaFuncSetAttribute(colcum_regions, cudaFuncAttributeMaxDynamicSharedMemorySize, CR_SMEM);
    }

    // Fork: weight precompute on side stream, data chain on main stream.
    cudaEventRecord(s_fork, 0);
    cudaStreamWaitEvent(s_side, s_fork, 0);

    precompA3<<<9, 256, 0, s_side>>>(Wq, Wk, Wv, Wo, Wout, bo, bout);
    precompB3<<<65, 256, 0, s_side>>>(Wqkv, bqkv, Wout);
    cudaEventRecord(s_join, s_side);

    ln_rowcum<<<BATCH*GRID, 256>>>(x, ln_g, ln_b);
    colcum_regions<<<BATCH*16, 256, CR_SMEM>>>();

    // Join: gemmU needs M/bu (side) + XN/regions (main).
    cudaStreamWaitEvent(0, s_join, 0);

    gemmU_fused<<<dim3(POSITIONS/128, 4), 256, GEMM_SMEM>>>();
    gemmY3<<<POSITIONS/64, 256, GEMMY_SMEM>>>(out);
}

// round 16
// speedup vs baseline: 1.0848x; 1.0008x over previous
#include <cuda_runtime.h>
#include <cuda_fp16.h>
#include <math.h>

// Problem constants
#define BATCH 8
#define NPOS 1024            // 32x32
#define DIM 128
#define HEADS 8
#define GRID 32              // H = W = 32
#define POSITIONS (BATCH*NPOS)   // 8192

#define GEMM_SMEM 71680      // gemmU: 2x(128x72) As + 2x(64x136) Bs; Uf(fp16 128x136) aliases Bs
#define GEMMY_SMEM 79872     // gemmY: 3x(64x72) + 3x(64x136) halfs
#define CR_SMEM 49152        // colcum_regions: 1024 pos x (8 dims + 4 pad) floats

// ---------------- scratch (static device memory; no allocs allowed) -------
__device__ float g_S[POSITIONS*DIM];             // row-cumsum image
__device__ float g_P1[DIM*DIM];                  // Wq @ Wk^T
__device__ float g_P2[DIM*DIM];                  // Wv @ Wo
__device__ float g_bu[HEADS*DIM];                // 0.25 * bqkv_h @ P1
__device__ float g_bfinal[DIM];

__device__ __half g_XNh[POSITIONS*DIM];          // layernormed x, fp16
__device__ __half g_Rh[POSITIONS*4*DIM];         // region means fp16 [pos][r][d]
__device__ __half g_Mh[DIM*HEADS*DIM];           // 0.25 * Wqkv_h @ P1, [128][1024]
__device__ __half g_W3h[HEADS*DIM*DIM];          // P2 @ Wout_h, [1024][128]
__device__ __half g_Ch[POSITIONS*HEADS*DIM];     // aggregated context, [8192][1024]

// ---------------- helpers ---------------------------------------------------
__device__ __forceinline__ unsigned smem_u32(const void* p) {
    return (unsigned)__cvta_generic_to_shared(p);
}
__device__ __forceinline__ void ldmatrix_x4(unsigned* r, unsigned addr) {
    asm volatile("ldmatrix.sync.aligned.m8n8.x4.shared.b16 {%0,%1,%2,%3}, [%4];"
        : "=r"(r[0]), "=r"(r[1]), "=r"(r[2]), "=r"(r[3]) : "r"(addr));
}
__device__ __forceinline__ void ldmatrix_x2t(unsigned* r, unsigned addr) {
    asm volatile("ldmatrix.sync.aligned.m8n8.x2.trans.shared.b16 {%0,%1}, [%2];"
        : "=r"(r[0]), "=r"(r[1]) : "r"(addr));
}
__device__ __forceinline__ void mma_f16(float* d, const unsigned* a, const unsigned* b) {
    asm volatile("mma.sync.aligned.m16n8k16.row.col.f32.f16.f16.f32 "
        "{%0,%1,%2,%3}, {%4,%5,%6,%7}, {%8,%9}, {%0,%1,%2,%3};"
        : "+f"(d[0]), "+f"(d[1]), "+f"(d[2]), "+f"(d[3])
        : "r"(a[0]), "r"(a[1]), "r"(a[2]), "r"(a[3]), "r"(b[0]), "r"(b[1]));
}
__device__ __forceinline__ void cp_async16(void* smem_dst, const void* gsrc) {
    asm volatile("cp.async.ca.shared.global [%0], [%1], 16;"
        :: "r"(smem_u32(smem_dst)), "l"(gsrc));
}

// ---------------- 64x64-tile fp32 matmul for weight precompute --------------
template<int MODE>
__device__ void mm64(const float* __restrict__ A, int lda,
                     const float* __restrict__ B, int ldb, int transB,
                     float* __restrict__ C, __half* __restrict__ Ch,
                     int ldc, int row0, int col0, float scale)
{
    __shared__ float As[16][64];
    __shared__ float Bs[16][68];
    const int tid = threadIdx.x;
    const int ty = tid >> 4, tx = tid & 15;
    float acc[4][4];
#pragma unroll
    for (int i = 0; i < 4; i++)
#pragma unroll
        for (int j = 0; j < 4; j++) acc[i][j] = 0.f;

    for (int k0 = 0; k0 < 128; k0 += 16) {
        for (int t = tid; t < 1024; t += 256) {
            int m = t >> 4, kk = t & 15;
            As[kk][m] = A[(row0+m)*lda + k0 + kk];
        }
        for (int t = tid; t < 1024; t += 256) {
            int kk = t >> 6, n = t & 63;
            Bs[kk][n] = transB ? B[(col0+n)*ldb + k0 + kk] : B[(k0+kk)*ldb + col0 + n];
        }
        __syncthreads();
#pragma unroll
        for (int kk = 0; kk < 16; kk++) {
            float a[4], b[4];
#pragma unroll
            for (int i = 0; i < 4; i++) a[i] = As[kk][ty*4+i];
#pragma unroll
            for (int j = 0; j < 4; j++) b[j] = Bs[kk][tx*4+j];
#pragma unroll
            for (int i = 0; i < 4; i++)
#pragma unroll
                for (int j = 0; j < 4; j++) acc[i][j] += a[i]*b[j];
        }
        __syncthreads();
    }
#pragma unroll
    for (int i = 0; i < 4; i++)
#pragma unroll
        for (int j = 0; j < 4; j++) {
            int r = row0 + ty*4 + i, c = col0 + tx*4 + j;
            if (MODE == 0) C[r*ldc + c] = acc[i][j];
            else           Ch[r*ldc + c] = __float2half(acc[i][j] * scale);
        }
}

// ---------------- precompute stage A: P1 = Wq@Wk^T, P2 = Wv@Wo, bfinal ------
__global__ void precompA3(const float* __restrict__ Wq, const float* __restrict__ Wk,
                          const float* __restrict__ Wv, const float* __restrict__ Wo,
                          const float* __restrict__ Wout, const float* __restrict__ bo,
                          const float* __restrict__ bout)
{
    int blk = blockIdx.x;
    if (blk < 4) {
        mm64<0>(Wq, DIM, Wk, DIM, 1, g_P1, 0, DIM, (blk>>1)*64, (blk&1)*64, 1.f);
    } else if (blk < 8) {
        int q = blk - 4;
        mm64<0>(Wv, DIM, Wo, DIM, 0, g_P2, 0, DIM, (q>>1)*64, (q&1)*64, 1.f);
    } else {
        __shared__ float part[256];
        int e = threadIdx.x & 127, half = threadIdx.x >> 7;
        float s = 0.f;
#pragma unroll 8
        for (int c = half*512; c < half*512 + 512; c++) s += bo[c & 127] * Wout[c*128 + e];
        part[threadIdx.x] = s;
        __syncthreads();
        if (half == 0) g_bfinal[e] = part[e] + part[128+e] + bout[e];
    }
}

// ---------------- precompute stage B: M_h, W3_h, bu -------------------------
__global__ void precompB3(const float* __restrict__ Wqkv, const float* __restrict__ bqkv,
                          const float* __restrict__ Wout)
{
    int blk = blockIdx.x;
    if (blk < 32) {
        int h = blk >> 2, q = blk & 3;
        mm64<1>(Wqkv + h*128, 3*HEADS*DIM, g_P1, DIM, 0, 0,
                g_Mh + h*DIM, HEADS*DIM, (q>>1)*64, (q&1)*64, 0.25f);
    } else if (blk < 64) {
        int h = (blk-32) >> 2, q = (blk-32) & 3;
        mm64<1>(g_P2, DIM, Wout + h*DIM*DIM, DIM, 0, 0,
                g_W3h + h*DIM*DIM, DIM, (q>>1)*64, (q&1)*64, 1.f);
    } else {
        for (int o = threadIdx.x; o < HEADS*DIM; o += 256) {
            int h = o >> 7, d2 = o & 127;
            float s = 0.f;
#pragma unroll 8
            for (int c = 0; c < 128; c++) s += bqkv[h*128+c] * g_P1[c*128+d2];
            g_bu[o] = 0.25f * s;
        }
    }
}

// ---------------- fused layernorm + row cumsum ------------------------------
__global__ __launch_bounds__(256) void ln_rowcum(const float* __restrict__ x,
                                                 const float* __restrict__ g,
                                                 const float* __restrict__ b)
{
    __shared__ float xs[32][128];
    const int bh = blockIdx.x;
    const int tid = threadIdx.x;
    const int wid = tid >> 5, lane = tid & 31;

    float4 g4 = ((const float4*)g)[lane];
    float4 b4 = ((const float4*)b)[lane];

#pragma unroll
    for (int i = 0; i < 4; i++) {
        int p = wid*4 + i;
        int row = bh*GRID + p;
        float4 v = ((const float4*)x)[row*32 + lane];
        float s  = v.x + v.y + v.z + v.w;
        float s2 = v.x*v.x + v.y*v.y + v.z*v.z + v.w*v.w;
#pragma unroll
        for (int o = 16; o > 0; o >>= 1) {
            s  += __shfl_xor_sync(0xffffffffu, s, o);
            s2 += __shfl_xor_sync(0xffffffffu, s2, o);
        }
        float mu = s * (1.f/128.f);
        float var = s2 * (1.f/128.f) - mu*mu;
        float inv = rsqrtf(var + 1e-5f);
        float4 xn;
        xn.x = (v.x - mu)*inv*g4.x + b4.x;
        xn.y = (v.y - mu)*inv*g4.y + b4.y;
        xn.z = (v.z - mu)*inv*g4.z + b4.z;
        xn.w = (v.w - mu)*inv*g4.w + b4.w;
        *(float4*)&xs[p][lane*4] = xn;
        *(__half2*)&g_XNh[row*DIM + lane*4]     = __floats2half2_rn(xn.x, xn.y);
        *(__half2*)&g_XNh[row*DIM + lane*4 + 2] = __floats2half2_rn(xn.z, xn.w);
    }
    __syncthreads();
    if (tid < 128) {
        float run = 0.f;
#pragma unroll
        for (int w = 0; w < GRID; w++) {
            run += xs[w][tid];
            g_S[(bh*GRID + w)*DIM + tid] = run;
        }
    }
}

// ---------------- fused column cumsum + region means ------------------------
__global__ __launch_bounds__(256) void colcum_regions()
{
    extern __shared__ float S[];                 // [pos][12], dims at [0..7]
    const int b  = blockIdx.x >> 4;
    const int d0 = (blockIdx.x & 15) * 8;
    const int tid = threadIdx.x;

#pragma unroll
    for (int i = 0; i < 4; i++) {
        int pos = i*256 + tid;
        const float4* src = (const float4*)&g_S[((size_t)b*NPOS + pos)*DIM + d0];
        float4 v0 = src[0], v1 = src[1];
        *(float4*)&S[pos*12]     = v0;
        *(float4*)&S[pos*12 + 4] = v1;
    }
    __syncthreads();

    {
        int w = tid >> 3, dd = tid & 7;
        float v[GRID];
#pragma unroll
        for (int h = 0; h < GRID; h++) v[h] = S[(h*GRID + w)*12 + dd];
        float run = 0.f;
#pragma unroll
        for (int h = 0; h < GRID; h++) { run += v[h]; v[h] = run; }
#pragma unroll
        for (int h = 0; h < GRID; h++) S[(h*GRID + w)*12 + dd] = v[h];
    }
    __syncthreads();

    if (tid < 128) {
        const int w  = tid >> 2;
        const int dd = (tid & 3) * 2;
        const float wp1 = (float)(w + 1), wr = (float)(GRID - w);

        float2 fHw  = *(float2*)&S[(31*GRID + w)*12 + dd];
        float2 fHW  = *(float2*)&S[(31*GRID + 31)*12 + dd];
        float2 fHw1 = make_float2(0.f, 0.f);
        if (w > 0) fHw1 = *(float2*)&S[(31*GRID + w-1)*12 + dd];

        float2 p_hw = make_float2(0.f, 0.f);
        float2 p_hw1 = make_float2(0.f, 0.f);
        float2 p_hW = make_float2(0.f, 0.f);

#pragma unroll 4
        for (int h = 0; h < GRID; h++) {
            float2 c_hw  = *(float2*)&S[(h*GRID + w)*12 + dd];
            float2 c_hW  = *(float2*)&S[(h*GRID + 31)*12 + dd];
            float2 c_hw1 = make_float2(0.f, 0.f);
            if (w > 0) c_hw1 = *(float2*)&S[(h*GRID + w-1)*12 + dd];

            float hp1 = (float)(h + 1), hr = (float)(GRID - h);
            float i1 = __fdividef(1.f, hp1*wp1);
            float i2 = __fdividef(1.f, hp1*wr);
            float i3 = __fdividef(1.f, hr*wp1);
            float i4 = __fdividef(1.f, hr*wr);

            __half* R = g_Rh + ((size_t)(b*NPOS + h*GRID + w))*4*DIM + d0 + dd;
            *(__half2*)&R[0]     = __floats2half2_rn(c_hw.x*i1, c_hw.y*i1);
            *(__half2*)&R[DIM]   = __floats2half2_rn((c_hW.x - c_hw1.x)*i2,
                                                     (c_hW.y - c_hw1.y)*i2);
            *(__half2*)&R[2*DIM] = __floats2half2_rn((fHw.x - p_hw.x)*i3,
                                                     (fHw.y - p_hw.y)*i3);
            *(__half2*)&R[3*DIM] = __floats2half2_rn(
                (fHW.x - p_hW.x - fHw1.x + p_hw1.x)*i4,
                (fHW.y - p_hW.y - fHw1.y + p_hw1.y)*i4);

            p_hw = c_hw; p_hw1 = c_hw1; p_hW = c_hW;
        }
    }
}

// ---------------- fused: U-GEMM, 2 heads per block + softmax + aggregate ----
// Epilogue v2: 8 positions in flight per warp, 4 lanes per position.
__global__ __launch_bounds__(256) void gemmU_fused()
{
    extern __shared__ char sbuf[];
    __half* As = (__half*)sbuf;                  // 2 x 128x72
    __half* Bs = (__half*)(sbuf + 36864);        // 2 x 64x136
    __half* Uf = (__half*)(sbuf + 36864);        // 128x136 fp16 (aliases Bs)

    const int tid = threadIdx.x;
    const int wid = tid >> 5, lane = tid & 31;
    const int wm = wid & 1, wn = wid >> 1;       // warp tile 64x32
    const int m0 = blockIdx.x * 128;

    auto LOAD_A = [&](int s, int buf) {
        int k0 = s * 64;
#pragma unroll
        for (int i = 0; i < 4; i++) {
            int c = tid + i*256;
            int row = c >> 3, col8 = (c & 7) * 8;
            cp_async16(As + buf*9216 + row*72 + col8,
                       g_XNh + (m0+row)*DIM + k0 + col8);
        }
    };
    auto LOAD_B = [&](int n0, int s, int buf) {
        int k0 = s * 64;
#pragma unroll
        for (int i = 0; i < 4; i++) {
            int c = tid + i*256;
            int kr = c >> 4, col8 = (c & 15) * 8;
            cp_async16(Bs + buf*8704 + kr*136 + col8,
                       g_Mh + (k0+kr)*(HEADS*DIM) + n0 + col8);
        }
    };

    const unsigned as_base = smem_u32(As), bs_base = smem_u32(Bs);
    unsigned a_off[4], b_off[4];
#pragma unroll
    for (int mt = 0; mt < 4; mt++)
        a_off[mt] = ((wm*64 + mt*16 + (lane & 15))*72 + (lane >> 4)*8)*2;
#pragma unroll
    for (int nt = 0; nt < 4; nt++)
        b_off[nt] = ((lane & 15)*136 + wn*32 + nt*8)*2;

    const int tr = lane >> 2, tc = (lane & 3)*2;
    const int r0 = wm*64, c0 = wn*32;

    // prologue: A (both stages) + B for first head
    {
        int n0 = blockIdx.y * 128;
        LOAD_A(0, 0); LOAD_B(n0, 0, 0);
        asm volatile("cp.async.commit_group;");
        LOAD_A(1, 1); LOAD_B(n0, 1, 1);
        asm volatile("cp.async.commit_group;");
    }

    for (int hh = 0; hh < 2; hh++) {
        const int h  = blockIdx.y + hh*4;
        const int n0 = h * 128;

        float acc[4][4][4];
#pragma unroll
        for (int mt = 0; mt < 4; mt++)
#pragma unroll
            for (int nt = 0; nt < 4; nt++)
#pragma unroll
                for (int q = 0; q < 4; q++) acc[mt][nt][q] = 0.f;

        auto COMPUTE = [&](int buf) {
#pragma unroll
            for (int kk = 0; kk < 4; kk++) {
                unsigned af[4][4];
#pragma unroll
                for (int mt = 0; mt < 4; mt++)
                    ldmatrix_x4(af[mt], as_base + buf*18432 + a_off[mt] + kk*32);
#pragma unroll
                for (int nt = 0; nt < 4; nt++) {
                    unsigned bfr[2];
                    ldmatrix_x2t(bfr, bs_base + buf*17408 + b_off[nt] + kk*4352);
#pragma unroll
                    for (int mt = 0; mt < 4; mt++) mma_f16(acc[mt][nt], af[mt], bfr);
                }
            }
        };

        asm volatile("cp.async.wait_group 1;");
        __syncthreads();
        COMPUTE(0);
        __syncthreads();
        asm volatile("cp.async.wait_group 0;");
        __syncthreads();
        COMPUTE(1);
        __syncthreads();                           // done reading Bs

        // ---- stage U (acc + bias) as fp16 into Uf (overwrites Bs) ---------
#pragma unroll
        for (int mt = 0; mt < 4; mt++)
#pragma unroll
            for (int nt = 0; nt < 4; nt++) {
                int row = r0 + mt*16 + tr, col = c0 + nt*8 + tc;
                float b0 = g_bu[n0 + col], b1 = g_bu[n0 + col + 1];
                *(__half2*)&Uf[row*136 + col] =
                    __floats2half2_rn(acc[mt][nt][0] + b0, acc[mt][nt][1] + b1);
                *(__half2*)&Uf[(row+8)*136 + col] =
                    __floats2half2_rn(acc[mt][nt][2] + b0, acc[mt][nt][3] + b1);
            }
        __syncthreads();                           // Uf complete

        // ---- epilogue v2: 4 lanes per position, 8 positions in flight -----
        {
            const int posq = lane >> 2, quarter = lane & 3;
#pragma unroll
            for (int bb2 = 0; bb2 < 2; bb2++) {
                int p = wid*16 + bb2*8 + posq;
                int gpos = m0 + p;
                const __half* Rp = g_Rh + (size_t)gpos*4*DIM + quarter*32;
                const __half* Up = Uf + p*136 + quarter*32;

                float s0 = 0.f, s1 = 0.f, s2 = 0.f, s3 = 0.f;
#pragma unroll
                for (int j = 0; j < 4; j++) {
                    uint4 uv  = *(const uint4*)&Up[j*8];
                    uint4 r0v = *(const uint4*)&Rp[j*8];
                    uint4 r1v = *(const uint4*)&Rp[DIM + j*8];
                    uint4 r2v = *(const uint4*)&Rp[2*DIM + j*8];
                    uint4 r3v = *(const uint4*)&Rp[3*DIM + j*8];
                    const __half2* uh = (const __half2*)&uv;
                    const __half2* h0 = (const __half2*)&r0v;
                    const __half2* h1 = (const __half2*)&r1v;
                    const __half2* h2 = (const __half2*)&r2v;
                    const __half2* h3 = (const __half2*)&r3v;
#pragma unroll
                    for (int t2 = 0; t2 < 4; t2++) {
                        float2 u  = __half22float2(uh[t2]);
                        float2 f0 = __half22float2(h0[t2]);
                        float2 f1 = __half22float2(h1[t2]);
                        float2 f2 = __half22float2(h2[t2]);
                        float2 f3 = __half22float2(h3[t2]);
                        s0 += u.x*f0.x + u.y*f0.y;
                        s1 += u.x*f1.x + u.y*f1.y;
                        s2 += u.x*f2.x + u.y*f2.y;
                        s3 += u.x*f3.x + u.y*f3.y;
                    }
                }
                // reduce over the 4 lanes of this position
                s0 += __shfl_xor_sync(0xffffffffu, s0, 1);
                s1 += __shfl_xor_sync(0xffffffffu, s1, 1);
                s2 += __shfl_xor_sync(0xffffffffu, s2, 1);
                s3 += __shfl_xor_sync(0xffffffffu, s3, 1);
                s0 += __shfl_xor_sync(0xffffffffu, s0, 2);
                s1 += __shfl_xor_sync(0xffffffffu, s1, 2);
                s2 += __shfl_xor_sync(0xffffffffu, s2, 2);
                s3 += __shfl_xor_sync(0xffffffffu, s3, 2);

                float m = fmaxf(fmaxf(s0, s1), fmaxf(s2, s3));
                float e0 = expf(s0 - m), e1 = expf(s1 - m);
                float e2 = expf(s2 - m), e3 = expf(s3 - m);
                float inv = 1.f / (e0 + e1 + e2 + e3);
                float p0 = e0*inv, p1 = e1*inv, p2 = e2*inv, p3 = e3*inv;

#pragma unroll
                for (int j = 0; j < 4; j++) {
                    uint4 r0v = *(const uint4*)&Rp[j*8];
                    uint4 r1v = *(const uint4*)&Rp[DIM + j*8];
                    uint4 r2v = *(const uint4*)&Rp[2*DIM + j*8];
                    uint4 r3v = *(const uint4*)&Rp[3*DIM + j*8];
                    const __half2* h0 = (const __half2*)&r0v;
                    const __half2* h1 = (const __half2*)&r1v;
                    const __half2* h2 = (const __half2*)&r2v;
                    const __half2* h3 = (const __half2*)&r3v;
                    uint4 o;
                    __half2* oh = (__half2*)&o;
#pragma unroll
                    for (int t2 = 0; t2 < 4; t2++) {
                        float2 f0 = __half22float2(h0[t2]);
                        float2 f1 = __half22float2(h1[t2]);
                        float2 f2 = __half22float2(h2[t2]);
                        float2 f3 = __half22float2(h3[t2]);
                        float cx = p0*f0.x + p1*f1.x + p2*f2.x + p3*f3.x;
                        float cy = p0*f0.y + p1*f1.y + p2*f2.y + p3*f3.y;
                        oh[t2] = __floats2half2_rn(cx, cy);
                    }
                    *(uint4*)&g_Ch[(size_t)gpos*(HEADS*DIM) + n0 + quarter*32 + j*8] = o;
                }
            }
        }

        // ---- prefetch B for second head (Uf dead after this sync) ---------
        if (hh == 0) {
            __syncthreads();                       // all warps done with Uf
            int n1 = (blockIdx.y + 4) * 128;
            LOAD_B(n1, 0, 0);
            asm volatile("cp.async.commit_group;");
            LOAD_B(n1, 1, 1);
            asm volatile("cp.async.commit_group;");
        }
    }
}

// ---------------- Y = C @ W3cat + bfinal -> out (3-stage pipeline) ----------
__global__ __launch_bounds__(256) void gemmY3(float* __restrict__ out)
{
    extern __shared__ char sbuf[];
    __half* As = (__half*)sbuf;                  // 3 x 64x72
    __half* Bs = (__half*)(sbuf + 27648);        // 3 x 64x136

    const int tid = threadIdx.x;
    const int wid = tid >> 5, lane = tid & 31;
    const int wm = wid & 1, wn = wid >> 1;       // warp tile 32x32
    const int m0 = blockIdx.x * 64;

    float acc[2][4][4];
#pragma unroll
    for (int mt = 0; mt < 2; mt++)
#pragma unroll
        for (int nt = 0; nt < 4; nt++)
#pragma unroll
            for (int q = 0; q < 4; q++) acc[mt][nt][q] = 0.f;

    auto LOAD = [&](int s, int buf) {
        int k0 = s * 64;
#pragma unroll
        for (int i = 0; i < 2; i++) {
            int c = tid + i*256;
            int row = c >> 3, col8 = (c & 7) * 8;
            cp_async16(As + buf*4608 + row*72 + col8,
                       g_Ch + (size_t)(m0+row)*(HEADS*DIM) + k0 + col8);
        }
#pragma unroll
        for (int i = 0; i < 4; i++) {
            int c = tid + i*256;
            int kr = c >> 4, col8 = (c & 15) * 8;
            cp_async16(Bs + buf*8704 + kr*136 + col8,
                       g_W3h + (k0+kr)*DIM + col8);
        }
        asm volatile("cp.async.commit_group;");
    };

    const unsigned as_base = smem_u32(As), bs_base = smem_u32(Bs);
    unsigned a_off[2], b_off[4];
#pragma unroll
    for (int mt = 0; mt < 2; mt++)
        a_off[mt] = ((wm*32 + mt*16 + (lane & 15))*72 + (lane >> 4)*8)*2;
#pragma unroll
    for (int nt = 0; nt < 4; nt++)
        b_off[nt] = ((lane & 15)*136 + wn*32 + nt*8)*2;

    auto COMPUTE = [&](int buf) {
#pragma unroll
        for (int kk = 0; kk < 4; kk++) {
            unsigned af[2][4];
#pragma unroll
            for (int mt = 0; mt < 2; mt++)
                ldmatrix_x4(af[mt], as_base + buf*9216 + a_off[mt] + kk*32);
#pragma unroll
            for (int nt = 0; nt < 4; nt++) {
                unsigned bfr[2];
                ldmatrix_x2t(bfr, bs_base + buf*17408 + b_off[nt] + kk*4352);
#pragma unroll
                for (int mt = 0; mt < 2; mt++) mma_f16(acc[mt][nt], af[mt], bfr);
            }
        }
    };

    LOAD(0, 0);
    LOAD(1, 1);
    for (int s = 0; s < 16; s++) {
        if (s < 15) asm volatile("cp.async.wait_group 1;");
        else        asm volatile("cp.async.wait_group 0;");
        __syncthreads();
        if (s < 14) LOAD(s+2, (s+2)%3);
        COMPUTE(s%3);
    }

    const int tr = lane >> 2, tc = (lane & 3)*2;
#pragma unroll
    for (int mt = 0; mt < 2; mt++)
#pragma unroll
        for (int nt = 0; nt < 4; nt++) {
            int row = m0 + wm*32 + mt*16 + tr, col = wn*32 + nt*8 + tc;
            float b0 = g_bfinal[col], b1 = g_bfinal[col+1];
            *(float2*)&out[(size_t)row*DIM + col] =
                make_float2(acc[mt][nt][0] + b0, acc[mt][nt][1] + b1);
            *(float2*)&out[(size_t)(row+8)*DIM + col] =
                make_float2(acc[mt][nt][2] + b0, acc[mt][nt][3] + b1);
        }
}

// ---------------- launch -----------------------------------------------------
extern "C" void kernel_launch(void* const* d_in, const int* in_sizes, int n_in,
                              void* d_out, int out_size)
{
    const float* x    = (const float*)d_in[0];
    const float* ln_g = (const float*)d_in[1];
    const float* ln_b = (const float*)d_in[2];
    const float* Wqkv = (const float*)d_in[3];
    const float* bqkv = (const float*)d_in[4];
    const float* Wq   = (const float*)d_in[5];
    const float* Wk   = (const float*)d_in[6];
    const float* Wv   = (const float*)d_in[7];
    const float* Wo   = (const float*)d_in[8];
    const float* bo   = (const float*)d_in[9];
    const float* Wout = (const float*)d_in[10];
    const float* bout = (const float*)d_in[11];
    float* out = (float*)d_out;

    // One-time setup (first call is the non-captured correctness run).
    static cudaStream_t s_side = nullptr;
    static cudaEvent_t s_fork = nullptr, s_join = nullptr;
    if (s_side == nullptr) {
        cudaStreamCreateWithFlags(&s_side, cudaStreamNonBlocking);
        cudaEventCreateWithFlags(&s_fork, cudaEventDisableTiming);
        cudaEventCreateWithFlags(&s_join, cudaEventDisableTiming);
        cudaFuncSetAttribute(gemmU_fused, cudaFuncAttributeMaxDynamicSharedMemorySize, GEMM_SMEM);
        cudaFuncSetAttribute(gemmY3,      cudaFuncAttributeMaxDynamicSharedMemorySize, GEMMY_SMEM);
        cudaFuncSetAttribute(colcum_regions, cudaFuncAttributeMaxDynamicSharedMemorySize, CR_SMEM);
    }

    // Fork: weight precompute on side stream, data chain on main stream.
    cudaEventRecord(s_fork, 0);
    cudaStreamWaitEvent(s_side, s_fork, 0);

    precompA3<<<9, 256, 0, s_side>>>(Wq, Wk, Wv, Wo, Wout, bo, bout);
    precompB3<<<65, 256, 0, s_side>>>(Wqkv, bqkv, Wout);
    cudaEventRecord(s_join, s_side);

    ln_rowcum<<<BATCH*GRID, 256>>>(x, ln_g, ln_b);
    colcum_regions<<<BATCH*16, 256, CR_SMEM>>>();

    // Join: gemmU needs M/bu (side) + XN/regions (main).
    cudaStreamWaitEvent(0, s_join, 0);

    gemmU_fused<<<dim3(POSITIONS/128, 4), 256, GEMM_SMEM>>>();
    gemmY3<<<POSITIONS/64, 256, GEMMY_SMEM>>>(out);
}